// round 15
// baseline (speedup 1.0000x reference)
#include <cuda_runtime.h>
#include <math.h>

// Problem dims
#define NSAMP 3
#define SSYM  512
#define FDIM  20
#define NLIN  11
#define NOUT  9
#define HID   2048
#define HIN   13824      // NSAMP*SSYM*NOUT
#define NO_   (NSAMP*SSYM)

// Scratch (device globals; no allocation allowed)
__device__ float g_v[HIN];
__device__ float g_h1[HID];
__device__ float g_h2[HID];
__device__ float g_h3[HID];
__device__ float g_lin[NO_];

__device__ __forceinline__ float sigmoidf_(float x) { return 1.0f / (1.0f + expf(-x)); }

// Weight load: L1-bypass (measured neutral; kept — weights have no reuse).
__device__ __forceinline__ float4 ldw(const float4* p) { return __ldcg(p); }

// ---------------------------------------------------------------------------
// Kernel 1: front end. One block per symbol s (512 blocks, 128 threads).
// ---------------------------------------------------------------------------
__global__ void front_kernel(const float* __restrict__ wax,
                             const float* __restrict__ blw,
                             const float* __restrict__ blb) {
    __shared__ float ctab[FDIM], stab[FDIM];
    __shared__ float sx [NSAMP][FDIM];
    __shared__ float sre[NSAMP][NLIN], sim[NSAMP][NLIN];
    __shared__ float szz[NSAMP][NOUT];

    const int s   = blockIdx.x;
    const int tid = threadIdx.x;

    if (tid < FDIM) {
        float th = 6.2831853071795864769f * (float)tid / 20.0f;
        ctab[tid] = cosf(th);
        stab[tid] = sinf(th);
    }
    __syncthreads();

    const int warp = tid >> 5, lane = tid & 31;
    if (warp < NSAMP) {
        const int b = warp;
        // InstanceNorm over F=20
        float x = 0.0f;
        if (lane < FDIM) x = wax[(b * SSYM + s) * FDIM + lane];
        float sum = x;
        #pragma unroll
        for (int off = 16; off; off >>= 1) sum += __shfl_xor_sync(0xffffffffu, sum, off);
        float mean = sum * (1.0f / 20.0f);
        float d = (lane < FDIM) ? (x - mean) : 0.0f;
        float sq = d * d;
        #pragma unroll
        for (int off = 16; off; off >>= 1) sq += __shfl_xor_sync(0xffffffffu, sq, off);
        float inv = rsqrtf(sq * (1.0f / 20.0f) + 1e-9f);
        if (lane < FDIM) sx[b][lane] = d * inv;
        __syncwarp();

        // rfft (direct DFT): X[m] = sum_n x[n] * exp(-2*pi*i*m*n/20)
        if (lane < NLIN) {
            float re = 0.0f, im = 0.0f;
            #pragma unroll
            for (int n = 0; n < FDIM; n++) {
                int r = (lane * n) % FDIM;
                float xn = sx[b][n];
                re += xn * ctab[r];
                im -= xn * stab[r];
            }
            sre[b][lane] = re;
            sim[b][lane] = im;
        }
        __syncwarp();

        // Bilinear + leaky relu
        if (lane < NOUT) {
            const float* Bk = blw + lane * (NLIN * NLIN);
            float z = 0.0f;
            #pragma unroll
            for (int i = 0; i < NLIN; i++) {
                float t = 0.0f;
                #pragma unroll
                for (int j = 0; j < NLIN; j++) t = fmaf(Bk[i * NLIN + j], sim[b][j], t);
                z = fmaf(sre[b][i], t, z);
            }
            z += blb[lane];
            z = z > 0.0f ? z : 0.01f * z;
            szz[b][lane] = z;
        }
    }
    __syncthreads();

    // Softmax across b (3 values) per (s,k)
    if (tid < NSAMP * NOUT) {
        const int b = tid / NOUT, k = tid % NOUT;
        float z0 = szz[0][k], z1 = szz[1][k], z2 = szz[2][k];
        float m  = fmaxf(z0, fmaxf(z1, z2));
        float e0 = expf(z0 - m), e1 = expf(z1 - m), e2 = expf(z2 - m);
        float den = e0 + e1 + e2;
        float eb  = (b == 0) ? e0 : (b == 1) ? e1 : e2;
        g_v[s * (NSAMP * NOUT) + b * NOUT + k] = eb / den;
    }
}

// ---------------------------------------------------------------------------
// Kernel 2: cell0 — UNCHANGED control (one block per j, NT=256, 55KB streams,
// measured ~5.4 TB/s). f-gate rows never read (c0=0), w_hh never read (h0=0).
// ---------------------------------------------------------------------------
template<int IN, int NT>
__global__ void __launch_bounds__(NT)
lstm_cell0_kernel(const float* __restrict__ W,
                  const float* __restrict__ b_ih,
                  const float* __restrict__ b_hh) {
    const float* __restrict__ x = g_v;
    float* __restrict__ hout = g_h1;

    const int j   = blockIdx.x;
    const int tid = threadIdx.x;

    const float4* __restrict__ x4 = (const float4*)x;
    const float4* __restrict__ w0 = (const float4*)(W + (size_t)j * IN);
    const float4* __restrict__ w1 = (const float4*)(W + (size_t)(j + 2 * HID) * IN);
    const float4* __restrict__ w2 = (const float4*)(W + (size_t)(j + 3 * HID) * IN);

    float acc0 = 0.0f, acc1 = 0.0f, acc2 = 0.0f;
    for (int t = tid; t < IN / 4; t += NT) {
        float4 v4 = x4[t];
        float4 a = ldw(w0 + t);
        acc0 += a.x * v4.x + a.y * v4.y + a.z * v4.z + a.w * v4.w;
        float4 b = ldw(w1 + t);
        acc1 += b.x * v4.x + b.y * v4.y + b.z * v4.z + b.w * v4.w;
        float4 c = ldw(w2 + t);
        acc2 += c.x * v4.x + c.y * v4.y + c.z * v4.z + c.w * v4.w;
    }

    #pragma unroll
    for (int off = 16; off; off >>= 1) {
        acc0 += __shfl_xor_sync(0xffffffffu, acc0, off);
        acc1 += __shfl_xor_sync(0xffffffffu, acc1, off);
        acc2 += __shfl_xor_sync(0xffffffffu, acc2, off);
    }
    __shared__ float red[NT / 32][3];
    const int warp = tid >> 5, lane = tid & 31;
    if (lane == 0) { red[warp][0] = acc0; red[warp][1] = acc1; red[warp][2] = acc2; }
    __syncthreads();
    if (tid == 0) {
        float di = 0.0f, dg = 0.0f, dob = 0.0f;
        #pragma unroll
        for (int w = 0; w < NT / 32; w++) { di += red[w][0]; dg += red[w][1]; dob += red[w][2]; }
        float gi = di  + b_ih[j]            + b_hh[j];
        float gg = dg  + b_ih[j + 2 * HID]  + b_hh[j + 2 * HID];
        float go = dob + b_ih[j + 3 * HID]  + b_hh[j + 3 * HID];
        float c  = sigmoidf_(gi) * tanhf(gg);
        hout[j]  = sigmoidf_(go) * tanhf(c);
    }
}

// ---------------------------------------------------------------------------
// Kernels 3-4: cell1/cell2 — 4 consecutive j rows per block.
// Rows are adjacent in memory, so each gate's read is ONE contiguous 32KB
// stream (vs 4 separate 8KB streams). x staged in smem, reused 12x.
// Grid = HID/4 = 512 blocks, NT=128.
// ---------------------------------------------------------------------------
#define IN4 (HID / 4)   // 512 float4 per row

template<int STAGE>
__global__ void __launch_bounds__(128)
lstm_cell4_kernel(const float* __restrict__ W,
                  const float* __restrict__ b_ih,
                  const float* __restrict__ b_hh) {
    const float* __restrict__ x = (STAGE == 1) ? g_h1 : g_h2;
    float* __restrict__ hout    = (STAGE == 1) ? g_h2 : g_h3;

    const int tid   = threadIdx.x;
    const int jbase = blockIdx.x * 4;

    __shared__ float4 xs[IN4];          // 8KB
    const float4* __restrict__ x4 = (const float4*)x;
    #pragma unroll
    for (int k = 0; k < IN4 / 128; k++) xs[k * 128 + tid] = x4[k * 128 + tid];
    __syncthreads();

    float acc[3][4];
    #pragma unroll
    for (int G = 0; G < 3; G++)
        #pragma unroll
        for (int r = 0; r < 4; r++) acc[G][r] = 0.0f;

    #pragma unroll
    for (int G = 0; G < 3; G++) {
        const size_t gofs = (G == 0) ? 0 : (G == 1) ? (size_t)2 * HID : (size_t)3 * HID;
        const float4* __restrict__ wb = (const float4*)W + (gofs + jbase) * IN4;
        #pragma unroll
        for (int r = 0; r < 4; r++) {
            float a = 0.0f;
            #pragma unroll
            for (int k = 0; k < 4; k++) {
                const int c = k * 128 + tid;
                float4 w  = ldw(wb + r * IN4 + c);
                float4 xv = xs[c];
                a += w.x * xv.x + w.y * xv.y + w.z * xv.z + w.w * xv.w;
            }
            acc[G][r] = a;
        }
    }

    // Reduce 12 values per block
    #pragma unroll
    for (int G = 0; G < 3; G++)
        #pragma unroll
        for (int r = 0; r < 4; r++)
            #pragma unroll
            for (int off = 16; off; off >>= 1)
                acc[G][r] += __shfl_xor_sync(0xffffffffu, acc[G][r], off);

    __shared__ float red[4][12];
    const int warp = tid >> 5, lane = tid & 31;
    if (lane == 0) {
        #pragma unroll
        for (int G = 0; G < 3; G++)
            #pragma unroll
            for (int r = 0; r < 4; r++) red[warp][G * 4 + r] = acc[G][r];
    }
    __syncthreads();
    if (tid < 4) {
        const int r = tid;
        const int j = jbase + r;
        float di = 0.0f, dg = 0.0f, dob = 0.0f;
        #pragma unroll
        for (int w = 0; w < 4; w++) {
            di  += red[w][0 * 4 + r];
            dg  += red[w][1 * 4 + r];
            dob += red[w][2 * 4 + r];
        }
        float gi = di  + b_ih[j]            + b_hh[j];
        float gg = dg  + b_ih[j + 2 * HID]  + b_hh[j + 2 * HID];
        float go = dob + b_ih[j + 3 * HID]  + b_hh[j + 3 * HID];
        float c  = sigmoidf_(gi) * tanhf(gg);
        hout[j]  = sigmoidf_(go) * tanhf(c);
    }
}

// ---------------------------------------------------------------------------
// Kernel 5: final linear — 4 consecutive rows per block (32KB streams).
// Grid = NO_/4 = 384, NT=128.
// ---------------------------------------------------------------------------
__global__ void __launch_bounds__(128)
linear4_kernel(const float* __restrict__ W, const float* __restrict__ bias) {
    const int tid   = threadIdx.x;
    const int jbase = blockIdx.x * 4;

    __shared__ float4 xs[IN4];          // 8KB
    const float4* __restrict__ x4 = (const float4*)g_h3;
    #pragma unroll
    for (int k = 0; k < IN4 / 128; k++) xs[k * 128 + tid] = x4[k * 128 + tid];
    __syncthreads();

    const float4* __restrict__ wb = (const float4*)W + (size_t)jbase * IN4;
    float acc[4];
    #pragma unroll
    for (int r = 0; r < 4; r++) {
        float a = 0.0f;
        #pragma unroll
        for (int k = 0; k < 4; k++) {
            const int c = k * 128 + tid;
            float4 w  = ldw(wb + r * IN4 + c);
            float4 xv = xs[c];
            a += w.x * xv.x + w.y * xv.y + w.z * xv.z + w.w * xv.w;
        }
        acc[r] = a;
    }

    #pragma unroll
    for (int r = 0; r < 4; r++)
        #pragma unroll
        for (int off = 16; off; off >>= 1)
            acc[r] += __shfl_xor_sync(0xffffffffu, acc[r], off);

    __shared__ float red[4][4];
    const int warp = tid >> 5, lane = tid & 31;
    if (lane == 0) {
        #pragma unroll
        for (int r = 0; r < 4; r++) red[warp][r] = acc[r];
    }
    __syncthreads();
    if (tid < 4) {
        float s = 0.0f;
        #pragma unroll
        for (int w = 0; w < 4; w++) s += red[w][tid];
        g_lin[jbase + tid] = s + bias[jbase + tid];
    }
}

// ---------------------------------------------------------------------------
// Kernel 6: inorm over S=512 + leaky relu + softmax over S. 3 blocks x 512.
// ---------------------------------------------------------------------------
__device__ __forceinline__ float blk512_sum(float v, float* red) {
    __syncthreads();
    const int warp = threadIdx.x >> 5, lane = threadIdx.x & 31;
    #pragma unroll
    for (int off = 16; off; off >>= 1) v += __shfl_xor_sync(0xffffffffu, v, off);
    if (lane == 0) red[warp] = v;
    __syncthreads();
    float r = (threadIdx.x < 16) ? red[threadIdx.x] : 0.0f;
    if (warp == 0) {
        #pragma unroll
        for (int off = 8; off; off >>= 1) r += __shfl_xor_sync(0xffffffffu, r, off);
        if (lane == 0) red[0] = r;
    }
    __syncthreads();
    return red[0];
}

__device__ __forceinline__ float blk512_max(float v, float* red) {
    __syncthreads();
    const int warp = threadIdx.x >> 5, lane = threadIdx.x & 31;
    #pragma unroll
    for (int off = 16; off; off >>= 1) v = fmaxf(v, __shfl_xor_sync(0xffffffffu, v, off));
    if (lane == 0) red[warp] = v;
    __syncthreads();
    float r = (threadIdx.x < 16) ? red[threadIdx.x] : -3.4e38f;
    if (warp == 0) {
        #pragma unroll
        for (int off = 8; off; off >>= 1) r = fmaxf(r, __shfl_xor_sync(0xffffffffu, r, off));
        if (lane == 0) red[0] = r;
    }
    __syncthreads();
    return red[0];
}

__global__ void post_kernel(float* __restrict__ out) {
    __shared__ float red[16];
    const int b = blockIdx.x, tid = threadIdx.x;
    float x = g_lin[b * SSYM + tid];

    float mean = blk512_sum(x, red) * (1.0f / 512.0f);
    float d    = x - mean;
    float var  = blk512_sum(d * d, red) * (1.0f / 512.0f);
    float xn   = d * rsqrtf(var + 1e-9f);
    float lr   = xn > 0.0f ? xn : 0.01f * xn;
    float mx   = blk512_max(lr, red);
    float e    = expf(lr - mx);
    float den  = blk512_sum(e, red);
    out[b * SSYM + tid] = e / den;
}

// ---------------------------------------------------------------------------
// Launch
// ---------------------------------------------------------------------------
extern "C" void kernel_launch(void* const* d_in, const int* in_sizes, int n_in,
                              void* d_out, int out_size) {
    const float* wax   = (const float*)d_in[0];
    const float* blw   = (const float*)d_in[1];
    const float* blb   = (const float*)d_in[2];
    const float* w_ih0 = (const float*)d_in[3];
    // d_in[4] = w_hh0 (unused: h0 == 0)
    const float* b_ih0 = (const float*)d_in[5];
    const float* b_hh0 = (const float*)d_in[6];
    const float* w_ih1 = (const float*)d_in[7];
    const float* b_ih1 = (const float*)d_in[9];
    const float* b_hh1 = (const float*)d_in[10];
    const float* w_ih2 = (const float*)d_in[11];
    const float* b_ih2 = (const float*)d_in[13];
    const float* b_hh2 = (const float*)d_in[14];
    const float* lin_w = (const float*)d_in[15];
    const float* lin_b = (const float*)d_in[16];

    front_kernel<<<SSYM, 128>>>(wax, blw, blb);
    // cell0: unchanged control (NT=256, 55KB row streams, ~5.4 TB/s)
    lstm_cell0_kernel<HIN, 256><<<HID, 256>>>(w_ih0, b_ih0, b_hh0);
    // cell1/cell2: 4 rows/block -> 32KB contiguous streams
    lstm_cell4_kernel<1><<<HID / 4, 128>>>(w_ih1, b_ih1, b_hh1);
    lstm_cell4_kernel<2><<<HID / 4, 128>>>(w_ih2, b_ih2, b_hh2);
    // linear: 4 rows/block
    linear4_kernel<<<NO_ / 4, 128>>>(lin_w, lin_b);
    post_kernel<<<NSAMP, 512>>>((float*)d_out);
}